// round 8
// baseline (speedup 1.0000x reference)
#include <cuda_runtime.h>
#include <cuda_bf16.h>
#include <cstdint>
#include <math.h>

// ---------------- problem constants ----------------
#define IN_DIM   512
#define OUT_DIM  512
#define BATCH    16384
#define N_KNOTS  12
#define W_TOTAL  576            // 512 spline windows (one per dim) + 64 base windows
#define NTILES   144            // k-tiles of 32 (= 4 windows of 8)
#define NTHREADS 256
#define STAGES   3
#define STAGE_F  8192           // floats: A 4096 + B 4096
#define SMEM_BYTES (STAGES * STAGE_F * 4)   // 98304

// ---------------- device scratch ----------------
__device__ float g_knots[IN_DIM * N_KNOTS];
__device__ float g_rden [IN_DIM * (N_KNOTS - 1)];
// fragment-major slabs: [tile128][window][1024]
__device__ float g_A[(size_t)(BATCH  / 128) * W_TOTAL * 1024];   // ~288 MB
__device__ float g_B[(size_t)(OUT_DIM / 128) * W_TOTAL * 1024];  // ~9 MB

// ---------------- helpers ----------------
__device__ __forceinline__ float f2tf32(float f) {
    uint32_t o;
    asm("cvt.rna.tf32.f32 %0, %1;" : "=r"(o) : "f"(f));
    return __uint_as_float(o);
}
// position of element (row-or-col rn 0..127, window element c 0..7) inside a slab
__device__ __forceinline__ int frag_off(int rn, int c) {
    return ((rn >> 4) * 128) + ((rn & 7) * 16) + ((c & 3) * 4) + ((c >> 2) * 2) + ((rn >> 3) & 1);
}
#define CP16(dst, src) asm volatile("cp.async.cg.shared.global [%0], [%1], 16;" :: "r"(dst), "l"(src) : "memory")
#define CP_COMMIT()    asm volatile("cp.async.commit_group;" ::: "memory")
#define CP_WAIT1()     asm volatile("cp.async.wait_group 1;" ::: "memory")
#define CP_WAIT0()     asm volatile("cp.async.wait_group 0;" ::: "memory")

__device__ __forceinline__ uint32_t smem_u32(const void* p) {
    uint32_t a;
    asm("{ .reg .u64 t; cvta.to.shared.u64 t, %1; cvt.u32.u64 %0, t; }" : "=r"(a) : "l"(p));
    return a;
}
__device__ __forceinline__ void mma4(float* c, float4 a, float b0, float b1) {
    asm volatile(
        "mma.sync.aligned.m16n8k8.row.col.f32.tf32.tf32.f32 "
        "{%0,%1,%2,%3}, {%4,%5,%6,%7}, {%8,%9}, {%0,%1,%2,%3};"
        : "+f"(c[0]), "+f"(c[1]), "+f"(c[2]), "+f"(c[3])
        : "r"(__float_as_uint(a.x)), "r"(__float_as_uint(a.y)),
          "r"(__float_as_uint(a.z)), "r"(__float_as_uint(a.w)),
          "r"(__float_as_uint(b0)), "r"(__float_as_uint(b1)));
}

// ---------------- kernel 1: knot precompute ----------------
__global__ void grid_precompute_kernel(const float* __restrict__ steps_log,
                                       const float* __restrict__ grid_start)
{
    int i = blockIdx.x * blockDim.x + threadIdx.x;
    if (i >= IN_DIM) return;
    float kn[N_KNOTS];
    kn[0] = grid_start[i];
    float acc = kn[0];
    #pragma unroll
    for (int j = 0; j < N_KNOTS - 1; j++) {
        float v  = steps_log[i * (N_KNOTS - 1) + j];
        float sp = fmaxf(v, 0.0f) + log1pf(expf(-fabsf(v)));
        acc += sp;
        kn[j + 1] = acc;
    }
    #pragma unroll
    for (int j = 0; j < N_KNOTS; j++) g_knots[i * N_KNOTS + j] = kn[j];
    #pragma unroll
    for (int j = 0; j < N_KNOTS - 1; j++)
        g_rden[i * (N_KNOTS - 1) + j] = 1.0f / (kn[j + 1] - kn[j] + 1e-8f);
}

// ---------------- kernel 2: weights -> fragment-major tf32 slabs ----------------
__global__ void convert_weights_kernel(const float* __restrict__ coeffs,
                                       const float* __restrict__ bw)
{
    const int stride = gridDim.x * blockDim.x;
    for (int i = blockIdx.x * blockDim.x + threadIdx.x; i < OUT_DIM * 4096; i += stride) {
        int o = i >> 12, rest = i & 4095, d = rest >> 3, c = rest & 7;
        g_B[((size_t)(o >> 7) * W_TOTAL + d) * 1024 + frag_off(o & 127, c)] = f2tf32(coeffs[i]);
    }
    for (int i = blockIdx.x * blockDim.x + threadIdx.x; i < OUT_DIM * 512; i += stride) {
        int o = i >> 9, d = i & 511;
        g_B[((size_t)(o >> 7) * W_TOTAL + 512 + (d >> 3)) * 1024 + frag_off(o & 127, d & 7)]
            = f2tf32(bw[i]);
    }
}

// ---------------- kernel 3: spline basis -> fragment-major slabs ----------------
__global__ __launch_bounds__(256)
void basis_kernel(const float* __restrict__ x)
{
    __shared__ float nat[8 * 1024];            // [dl][row][c] natural layout
    const int t  = threadIdx.x;
    const int g  = blockIdx.x;                 // dim group (8 dims)
    const int Tm = blockIdx.y;

    #pragma unroll
    for (int p = 0; p < 4; p++) {
        const int lin = p * 256 + t;
        const int row = lin & 127, dl = lin >> 7;
        const int d = g * 8 + dl;
        const float xv = __ldg(x + (size_t)(Tm * 128 + row) * IN_DIM + d);

        float k[N_KNOTS], rd[N_KNOTS - 1];
        #pragma unroll
        for (int j = 0; j < N_KNOTS; j++) k[j] = g_knots[d * N_KNOTS + j];
        #pragma unroll
        for (int j = 0; j < N_KNOTS - 1; j++) rd[j] = g_rden[d * (N_KNOTS - 1) + j];

        float tb[11];
        #pragma unroll
        for (int j = 0; j < 11; j++)
            tb[j] = (xv >= k[j] && xv < k[j + 1]) ? 1.0f : 0.0f;
        #pragma unroll
        for (int j = 0; j < 10; j++)
            tb[j] = (xv - k[j]) * rd[j] * tb[j] + (k[j + 2] - xv) * rd[j + 1] * tb[j + 1];
        #pragma unroll
        for (int j = 0; j < 9; j++)
            tb[j] = (xv - k[j]) * rd[j] * tb[j] + (k[j + 3] - xv) * rd[j + 2] * tb[j + 1];
        float bb[8];
        #pragma unroll
        for (int j = 0; j < 8; j++)
            bb[j] = f2tf32((xv - k[j]) * rd[j] * tb[j] + (k[j + 4] - xv) * rd[j + 3] * tb[j + 1]);

        float4* dst = (float4*)&nat[dl * 1024 + row * 8];
        dst[0] = make_float4(bb[0], bb[1], bb[2], bb[3]);
        dst[1] = make_float4(bb[4], bb[5], bb[6], bb[7]);
    }
    __syncthreads();

    // permuted copy-out: fragment-major, linear float4 stores
    float4* gdst = (float4*)(g_A + ((size_t)Tm * W_TOTAL + g * 8) * 1024);
    #pragma unroll
    for (int j = 0; j < 8; j++) {
        const int fidx = j * 256 + t;
        const int dl = fidx >> 8;
        const int oin = (fidx & 255) * 4;
        const int g16 = oin >> 7, qq = (oin >> 4) & 7, rr = (oin >> 2) & 3;
        const int row0 = g16 * 16 + qq;
        const float* s = &nat[dl * 1024];
        float4 v;
        v.x = s[ row0      * 8 + rr];
        v.y = s[(row0 + 8) * 8 + rr];
        v.z = s[ row0      * 8 + rr + 4];
        v.w = s[(row0 + 8) * 8 + rr + 4];
        gdst[fidx] = v;
    }
}

// ---------------- kernel 4: silu(x) -> fragment-major base slabs ----------------
__global__ __launch_bounds__(256)
void silu_kernel(const float* __restrict__ x)
{
    __shared__ float nat[128 * 64];            // [row][drel]
    const int t  = threadIdx.x;
    const int jg = blockIdx.x;                 // 64-dim group (8 windows)
    const int Tm = blockIdx.y;

    #pragma unroll
    for (int p = 0; p < 32; p++) {
        const int lin = p * 256 + t;
        const int drel = lin & 63, row = lin >> 6;
        const float xv = __ldg(x + (size_t)(Tm * 128 + row) * IN_DIM + jg * 64 + drel);
        nat[row * 64 + drel] = f2tf32(xv / (1.0f + expf(-xv)));
    }
    __syncthreads();

    float4* gdst = (float4*)(g_A + ((size_t)Tm * W_TOTAL + 512 + jg * 8) * 1024);
    #pragma unroll
    for (int j = 0; j < 8; j++) {
        const int fidx = j * 256 + t;
        const int wrel = fidx >> 8;
        const int oin = (fidx & 255) * 4;
        const int g16 = oin >> 7, qq = (oin >> 4) & 7, rr = (oin >> 2) & 3;
        const int row0 = g16 * 16 + qq;
        float4 v;
        v.x = nat[ row0      * 64 + wrel * 8 + rr];
        v.y = nat[(row0 + 8) * 64 + wrel * 8 + rr];
        v.z = nat[ row0      * 64 + wrel * 8 + rr + 4];
        v.w = nat[(row0 + 8) * 64 + wrel * 8 + rr + 4];
        gdst[fidx] = v;
    }
}

// ---------------- kernel 5: tf32 mma.sync GEMM, fragment-major, 3-stage ----------------
__global__ __launch_bounds__(NTHREADS, 2)
void kan_gemm_kernel(const float* __restrict__ x,
                     const float* __restrict__ res_scale,
                     float* __restrict__ out)
{
    extern __shared__ float smem[];
    const int t = threadIdx.x, warp = t >> 5, lane = t & 31;
    const int q = lane >> 2, r = lane & 3;
    const int warpM = warp >> 1, warpN = warp & 1;        // 4 x 2 warps
    const int Tn = blockIdx.x, Tm = blockIdx.y;           // Tn fastest -> A L2 reuse
    const int m_blk = Tm * 128, n_blk = Tn * 128;

    const float* Ab = g_A + (size_t)Tm * (W_TOTAL * 1024);
    const float* Bb = g_B + (size_t)Tn * (W_TOTAL * 1024);
    const uint32_t sb = smem_u32(smem);

    auto loader = [&](int kt, int stage) {
        const float* as = Ab + (size_t)kt * 4096;
        const float* bs = Bb + (size_t)kt * 4096;
        const uint32_t sa = sb + stage * (STAGE_F * 4);
        #pragma unroll
        for (int i = 0; i < 4; i++) CP16(sa + (i * 256 + t) * 16, as + (i * 256 + t) * 4);
        #pragma unroll
        for (int i = 0; i < 4; i++) CP16(sa + 16384 + (i * 256 + t) * 16, bs + (i * 256 + t) * 4);
        CP_COMMIT();
    };

    float acc[2][8][4];
    #pragma unroll
    for (int i = 0; i < 2; i++)
        #pragma unroll
        for (int j = 0; j < 8; j++)
            #pragma unroll
            for (int v = 0; v < 4; v++) acc[i][j][v] = 0.0f;

    loader(0, 0);
    loader(1, 1);

    for (int kt = 0; kt < NTILES; kt++) {
        if (kt < NTILES - 1) CP_WAIT1(); else CP_WAIT0();
        __syncthreads();
        if (kt + 2 < NTILES) loader(kt + 2, (kt + 2) % 3);

        const float* As = smem + (kt % 3) * STAGE_F;
        const float* Bs = As + 4096;

        #pragma unroll
        for (int ws = 0; ws < 4; ws++) {
            const float4 a0 = *(const float4*)(As + ws * 1024 + (warpM * 2 + 0) * 128 + lane * 4);
            const float4 a1 = *(const float4*)(As + ws * 1024 + (warpM * 2 + 1) * 128 + lane * 4);
            #pragma unroll
            for (int nfp = 0; nfp < 4; nfp++) {
                const float4 b = *(const float4*)(Bs + ws * 1024 + (warpN * 4 + nfp) * 128 + lane * 4);
                mma4(acc[0][2 * nfp],     a0, b.x, b.z);
                mma4(acc[0][2 * nfp + 1], a0, b.y, b.w);
                mma4(acc[1][2 * nfp],     a1, b.x, b.z);
                mma4(acc[1][2 * nfp + 1], a1, b.y, b.w);
            }
        }
    }

    // ---- epilogue: + rs*x, tanh ----
    const float rs = __ldg(res_scale);
    #pragma unroll
    for (int mf = 0; mf < 2; mf++) {
        #pragma unroll
        for (int rr2 = 0; rr2 < 2; rr2++) {
            const int rowg = m_blk + warpM * 32 + mf * 16 + rr2 * 8 + q;
            #pragma unroll
            for (int nf = 0; nf < 8; nf++) {
                const int col = n_blk + warpN * 64 + nf * 8 + r * 2;
                const size_t idx = (size_t)rowg * OUT_DIM + col;
                const float2 xv = __ldg((const float2*)(x + idx));
                float2 o;
                o.x = tanhf(acc[mf][nf][rr2 * 2 + 0] + rs * xv.x);
                o.y = tanhf(acc[mf][nf][rr2 * 2 + 1] + rs * xv.y);
                *(float2*)(out + idx) = o;
            }
        }
    }
}

// ---------------------------------------------------------------------------
extern "C" void kernel_launch(void* const* d_in, const int* in_sizes, int n_in,
                              void* d_out, int out_size)
{
    const float* x           = (const float*)d_in[0];
    const float* coeffs      = (const float*)d_in[1];
    const float* base_weight = (const float*)d_in[2];
    const float* steps_log   = (const float*)d_in[3];
    const float* grid_start  = (const float*)d_in[4];
    const float* res_scale   = (const float*)d_in[5];
    float* out = (float*)d_out;

    grid_precompute_kernel<<<2, 256>>>(steps_log, grid_start);
    convert_weights_kernel<<<512, 256>>>(coeffs, base_weight);
    basis_kernel<<<dim3(64, 128), 256>>>(x);
    silu_kernel<<<dim3(8, 128), 256>>>(x);

    cudaFuncSetAttribute(kan_gemm_kernel,
                         cudaFuncAttributeMaxDynamicSharedMemorySize, SMEM_BYTES);
    kan_gemm_kernel<<<dim3(4, 128), NTHREADS, SMEM_BYTES>>>(x, res_scale, out);
}

// round 12
// speedup vs baseline: 1.7039x; 1.7039x over previous
#include <cuda_runtime.h>
#include <cuda_bf16.h>
#include <cstdint>
#include <math.h>

// ---------------- problem constants ----------------
#define IN_DIM   512
#define OUT_DIM  512
#define BATCH    16384
#define N_KNOTS  12
#define W_TOTAL  576            // 512 spline windows + 64 base windows
#define NTILES   144            // k-tiles of 32 (= 4 windows of 8)
#define NTHREADS 256
#define STAGES   3
#define STAGE_F  8192           // floats: A 4096 + B 4096
#define SMEM_BYTES (STAGES * STAGE_F * 4)   // 98304

// ---------------- device scratch ----------------
__device__ float g_knots[IN_DIM * N_KNOTS];
__device__ float g_rden [IN_DIM * (N_KNOTS - 1)];
// fragment-major slabs: [tile128][window][1024]
__device__ float g_A[(size_t)(BATCH  / 128) * W_TOTAL * 1024];   // ~288 MB
__device__ float g_B[(size_t)(OUT_DIM / 128) * W_TOTAL * 1024];  // ~9 MB

// ---------------- helpers ----------------
__device__ __forceinline__ float f2tf32(float f) {
    uint32_t o;
    asm("cvt.rna.tf32.f32 %0, %1;" : "=r"(o) : "f"(f));
    return __uint_as_float(o);
}
#define CP16(dst, src) asm volatile("cp.async.cg.shared.global [%0], [%1], 16;" :: "r"(dst), "l"(src) : "memory")
#define CP_COMMIT()    asm volatile("cp.async.commit_group;" ::: "memory")
#define CP_WAIT1()     asm volatile("cp.async.wait_group 1;" ::: "memory")
#define CP_WAIT0()     asm volatile("cp.async.wait_group 0;" ::: "memory")

__device__ __forceinline__ uint32_t smem_u32(const void* p) {
    uint32_t a;
    asm("{ .reg .u64 t; cvta.to.shared.u64 t, %1; cvt.u32.u64 %0, t; }" : "=r"(a) : "l"(p));
    return a;
}
__device__ __forceinline__ void mma4(float* c, float4 a, float b0, float b1) {
    asm volatile(
        "mma.sync.aligned.m16n8k8.row.col.f32.tf32.tf32.f32 "
        "{%0,%1,%2,%3}, {%4,%5,%6,%7}, {%8,%9}, {%0,%1,%2,%3};"
        : "+f"(c[0]), "+f"(c[1]), "+f"(c[2]), "+f"(c[3])
        : "r"(__float_as_uint(a.x)), "r"(__float_as_uint(a.y)),
          "r"(__float_as_uint(a.z)), "r"(__float_as_uint(a.w)),
          "r"(__float_as_uint(b0)), "r"(__float_as_uint(b1)));
}

// degree-3 basis, verbatim reference recursion
__device__ __forceinline__ void eval_basis(float xv, const float* __restrict__ k,
                                           const float* __restrict__ rd,
                                           float* __restrict__ bb)
{
    float t[11];
    #pragma unroll
    for (int j = 0; j < 11; j++)
        t[j] = (xv >= k[j] && xv < k[j + 1]) ? 1.0f : 0.0f;
    #pragma unroll
    for (int j = 0; j < 10; j++)
        t[j] = (xv - k[j]) * rd[j] * t[j] + (k[j + 2] - xv) * rd[j + 1] * t[j + 1];
    #pragma unroll
    for (int j = 0; j < 9; j++)
        t[j] = (xv - k[j]) * rd[j] * t[j] + (k[j + 3] - xv) * rd[j + 2] * t[j + 1];
    #pragma unroll
    for (int j = 0; j < 8; j++)
        bb[j] = f2tf32((xv - k[j]) * rd[j] * t[j] + (k[j + 4] - xv) * rd[j + 3] * t[j + 1]);
}

// ---------------- kernel 1: knot precompute ----------------
__global__ void grid_precompute_kernel(const float* __restrict__ steps_log,
                                       const float* __restrict__ grid_start)
{
    int i = blockIdx.x * blockDim.x + threadIdx.x;
    if (i >= IN_DIM) return;
    float kn[N_KNOTS];
    kn[0] = grid_start[i];
    float acc = kn[0];
    #pragma unroll
    for (int j = 0; j < N_KNOTS - 1; j++) {
        float v  = steps_log[i * (N_KNOTS - 1) + j];
        float sp = fmaxf(v, 0.0f) + log1pf(expf(-fabsf(v)));
        acc += sp;
        kn[j + 1] = acc;
    }
    #pragma unroll
    for (int j = 0; j < N_KNOTS; j++) g_knots[i * N_KNOTS + j] = kn[j];
    #pragma unroll
    for (int j = 0; j < N_KNOTS - 1; j++)
        g_rden[i * (N_KNOTS - 1) + j] = 1.0f / (kn[j + 1] - kn[j] + 1e-8f);
}

// ---------------- kernel 2: weights -> fragment-major slabs (direct) ----------------
// grid (72, 4). g<64: spline windows from coeffs; g>=64: base windows from bw.
// thread item (dl, o-pair): reads 8 floats x 2 rows, writes one 64B chunk.
__global__ __launch_bounds__(256)
void convert_B_kernel(const float* __restrict__ coeffs,
                      const float* __restrict__ bw)
{
    const int t = threadIdx.x, g = blockIdx.x, Tn = blockIdx.y;
    #pragma unroll
    for (int m = 0; m < 2; m++) {
        const int i  = m * 256 + t;
        const int dl = i >> 6, pr = i & 63;
        const int p16 = pr >> 3, p8 = pr & 7;
        const int o0 = Tn * 128 + p16 * 16 + p8, o1 = o0 + 8;
        float4 a0, a1, b0, b1;   // a=low4, b=high4 per row
        int window;
        if (g < 64) {
            const int d = g * 8 + dl;
            const float4* p0 = (const float4*)(coeffs + (size_t)o0 * 4096 + d * 8);
            const float4* p1 = (const float4*)(coeffs + (size_t)o1 * 4096 + d * 8);
            a0 = p0[0]; b0 = p0[1]; a1 = p1[0]; b1 = p1[1];
            window = d;
        } else {
            const int w = (g - 64) * 8 + dl;
            const float4* p0 = (const float4*)(bw + (size_t)o0 * 512 + w * 8);
            const float4* p1 = (const float4*)(bw + (size_t)o1 * 512 + w * 8);
            a0 = p0[0]; b0 = p0[1]; a1 = p1[0]; b1 = p1[1];
            window = 512 + w;
        }
        float4* dst = (float4*)(g_B + ((size_t)Tn * W_TOTAL + window) * 1024
                                + p16 * 128 + p8 * 16);
        dst[0] = make_float4(f2tf32(a0.x), f2tf32(a1.x), f2tf32(b0.x), f2tf32(b1.x));
        dst[1] = make_float4(f2tf32(a0.y), f2tf32(a1.y), f2tf32(b0.y), f2tf32(b1.y));
        dst[2] = make_float4(f2tf32(a0.z), f2tf32(a1.z), f2tf32(b0.z), f2tf32(b1.z));
        dst[3] = make_float4(f2tf32(a0.w), f2tf32(a1.w), f2tf32(b0.w), f2tf32(b1.w));
    }
}

// ---------------- kernel 3: A slabs (basis + silu), direct fragment writes ----------------
// grid (72, 128). g<64: 8 spline dims; g>=64: 8 base windows (64 dims).
__global__ __launch_bounds__(256)
void gen_A_kernel(const float* __restrict__ x)
{
    __shared__ float sh[128 * 65];     // silu path x tile; spline path uses prefix
    const int t = threadIdx.x, g = blockIdx.x, Tm = blockIdx.y;

    if (g < 64) {
        // ---- spline: dims g*8 .. g*8+7 ----
        float* xs = sh;                         // [row][dl] stride 9 (1152 floats)
        float* kk = sh + 1152;                  // 8 x 12
        float* rr = sh + 1152 + 96;             // 8 x 11
        #pragma unroll
        for (int it = 0; it < 4; it++) {
            const int idx = it * 256 + t;
            const int row = idx >> 3, dl = idx & 7;
            xs[row * 9 + dl] = __ldg(x + (size_t)(Tm * 128 + row) * IN_DIM + g * 8 + dl);
        }
        if (t < 96)               kk[t]      = g_knots[g * 8 * N_KNOTS + t];
        else if (t < 96 + 88)     rr[t - 96] = g_rden[g * 8 * (N_KNOTS - 1) + (t - 96)];
        __syncthreads();

        #pragma unroll
        for (int m = 0; m < 2; m++) {
            const int i  = m * 256 + t;
            const int dl = i >> 6, pr = i & 63;
            const int p16 = pr >> 3, p8 = pr & 7;
            const int row0 = p16 * 16 + p8;
            float bb0[8], bb1[8];
            eval_basis(xs[row0 * 9 + dl],       kk + dl * 12, rr + dl * 11, bb0);
            eval_basis(xs[(row0 + 8) * 9 + dl], kk + dl * 12, rr + dl * 11, bb1);
            float4* dst = (float4*)(g_A + ((size_t)Tm * W_TOTAL + g * 8 + dl) * 1024
                                    + p16 * 128 + p8 * 16);
            #pragma unroll
            for (int j = 0; j < 4; j++)
                dst[j] = make_float4(bb0[j], bb1[j], bb0[j + 4], bb1[j + 4]);
        }
    } else {
        // ---- silu: dims (g-64)*64 .. +63 -> windows 512 + (g-64)*8 .. +7 ----
        const int d0 = (g - 64) * 64;
        #pragma unroll
        for (int it = 0; it < 32; it++) {
            const int idx = it * 256 + t;
            const int row = idx >> 6, dd = idx & 63;
            sh[row * 65 + dd] = __ldg(x + (size_t)(Tm * 128 + row) * IN_DIM + d0 + dd);
        }
        __syncthreads();

        #pragma unroll
        for (int m = 0; m < 2; m++) {
            const int i  = m * 256 + t;
            const int wl = i >> 6, pr = i & 63;
            const int p16 = pr >> 3, p8 = pr & 7;
            const int row0 = p16 * 16 + p8;
            float s0[8], s1[8];
            #pragma unroll
            for (int c = 0; c < 8; c++) {
                const float v0 = sh[row0 * 65 + wl * 8 + c];
                const float v1 = sh[(row0 + 8) * 65 + wl * 8 + c];
                s0[c] = f2tf32(v0 / (1.0f + expf(-v0)));
                s1[c] = f2tf32(v1 / (1.0f + expf(-v1)));
            }
            float4* dst = (float4*)(g_A + ((size_t)Tm * W_TOTAL + 512 + (g - 64) * 8 + wl) * 1024
                                    + p16 * 128 + p8 * 16);
            #pragma unroll
            for (int j = 0; j < 4; j++)
                dst[j] = make_float4(s0[j], s1[j], s0[j + 4], s1[j + 4]);
        }
    }
}

// ---------------- kernel 4: tf32 mma.sync GEMM, fragment-major, 3-stage ----------------
__global__ __launch_bounds__(NTHREADS, 2)
void kan_gemm_kernel(const float* __restrict__ x,
                     const float* __restrict__ res_scale,
                     float* __restrict__ out)
{
    extern __shared__ float smem[];
    const int t = threadIdx.x, warp = t >> 5, lane = t & 31;
    const int q = lane >> 2, r = lane & 3;
    const int warpM = warp >> 1, warpN = warp & 1;        // 4 x 2 warps
    const int Tn = blockIdx.x, Tm = blockIdx.y;           // Tn fastest -> A L2 reuse
    const int m_blk = Tm * 128, n_blk = Tn * 128;

    const float* Ab = g_A + (size_t)Tm * (W_TOTAL * 1024);
    const float* Bb = g_B + (size_t)Tn * (W_TOTAL * 1024);
    const uint32_t sb = smem_u32(smem);

    auto loader = [&](int kt, int stage) {
        const float* as = Ab + (size_t)kt * 4096;
        const float* bs = Bb + (size_t)kt * 4096;
        const uint32_t sa = sb + stage * (STAGE_F * 4);
        #pragma unroll
        for (int i = 0; i < 4; i++) CP16(sa + (i * 256 + t) * 16, as + (i * 256 + t) * 4);
        #pragma unroll
        for (int i = 0; i < 4; i++) CP16(sa + 16384 + (i * 256 + t) * 16, bs + (i * 256 + t) * 4);
        CP_COMMIT();
    };

    float acc[2][8][4];
    #pragma unroll
    for (int i = 0; i < 2; i++)
        #pragma unroll
        for (int j = 0; j < 8; j++)
            #pragma unroll
            for (int v = 0; v < 4; v++) acc[i][j][v] = 0.0f;

    loader(0, 0);
    loader(1, 1);

    for (int kt = 0; kt < NTILES; kt++) {
        if (kt < NTILES - 1) CP_WAIT1(); else CP_WAIT0();
        __syncthreads();
        if (kt + 2 < NTILES) loader(kt + 2, (kt + 2) % 3);

        const float* As = smem + (kt % 3) * STAGE_F;
        const float* Bs = As + 4096;

        #pragma unroll
        for (int ws = 0; ws < 4; ws++) {
            const float4 a0 = *(const float4*)(As + ws * 1024 + (warpM * 2 + 0) * 128 + lane * 4);
            const float4 a1 = *(const float4*)(As + ws * 1024 + (warpM * 2 + 1) * 128 + lane * 4);
            #pragma unroll
            for (int nfp = 0; nfp < 4; nfp++) {
                const float4 b = *(const float4*)(Bs + ws * 1024 + (warpN * 4 + nfp) * 128 + lane * 4);
                mma4(acc[0][2 * nfp],     a0, b.x, b.z);
                mma4(acc[0][2 * nfp + 1], a0, b.y, b.w);
                mma4(acc[1][2 * nfp],     a1, b.x, b.z);
                mma4(acc[1][2 * nfp + 1], a1, b.y, b.w);
            }
        }
    }

    // ---- epilogue: + rs*x, tanh ----
    const float rs = __ldg(res_scale);
    #pragma unroll
    for (int mf = 0; mf < 2; mf++) {
        #pragma unroll
        for (int rr2 = 0; rr2 < 2; rr2++) {
            const int rowg = m_blk + warpM * 32 + mf * 16 + rr2 * 8 + q;
            #pragma unroll
            for (int nf = 0; nf < 8; nf++) {
                const int col = n_blk + warpN * 64 + nf * 8 + r * 2;
                const size_t idx = (size_t)rowg * OUT_DIM + col;
                const float2 xv = __ldg((const float2*)(x + idx));
                float2 o;
                o.x = tanhf(acc[mf][nf][rr2 * 2 + 0] + rs * xv.x);
                o.y = tanhf(acc[mf][nf][rr2 * 2 + 1] + rs * xv.y);
                *(float2*)(out + idx) = o;
            }
        }
    }
}

// ---------------------------------------------------------------------------
extern "C" void kernel_launch(void* const* d_in, const int* in_sizes, int n_in,
                              void* d_out, int out_size)
{
    const float* x           = (const float*)d_in[0];
    const float* coeffs      = (const float*)d_in[1];
    const float* base_weight = (const float*)d_in[2];
    const float* steps_log   = (const float*)d_in[3];
    const float* grid_start  = (const float*)d_in[4];
    const float* res_scale   = (const float*)d_in[5];
    float* out = (float*)d_out;

    grid_precompute_kernel<<<2, 256>>>(steps_log, grid_start);
    convert_B_kernel<<<dim3(72, 4), 256>>>(coeffs, base_weight);
    gen_A_kernel<<<dim3(72, 128), 256>>>(x);

    cudaFuncSetAttribute(kan_gemm_kernel,
                         cudaFuncAttributeMaxDynamicSharedMemorySize, SMEM_BYTES);
    kan_gemm_kernel<<<dim3(4, 128), NTHREADS, SMEM_BYTES>>>(x, res_scale, out);
}

// round 14
// speedup vs baseline: 1.8694x; 1.0971x over previous
#include <cuda_runtime.h>
#include <cuda_bf16.h>
#include <cstdint>
#include <math.h>

// ---------------- problem constants ----------------
#define IN_DIM   512
#define OUT_DIM  512
#define BATCH    16384
#define N_KNOTS  12
#define W_TOTAL  576            // 512 spline windows + 64 base windows
#define NTILES   144            // k-tiles of 32 (= 4 windows of 8)
#define NTHREADS 256
#define STAGE_F  6144           // floats per stage: A 4096 + B 2048
#define SMEM_BYTES (3 * STAGE_F * 4)   // 73728

// ---------------- device scratch ----------------
__device__ float g_knots[IN_DIM * N_KNOTS];
__device__ float g_rden [IN_DIM * (N_KNOTS - 1)];
// A: [tile128][window][1024] fragment-major ; B: [tile64][window][512]
__device__ float g_A[(size_t)(BATCH  / 128) * W_TOTAL * 1024];   // ~288 MB
__device__ float g_B[(size_t)(OUT_DIM / 64)  * W_TOTAL * 512];   // ~9 MB

// ---------------- helpers ----------------
__device__ __forceinline__ float f2tf32(float f) {
    uint32_t o;
    asm("cvt.rna.tf32.f32 %0, %1;" : "=r"(o) : "f"(f));
    return __uint_as_float(o);
}
#define CP16(dst, src) asm volatile("cp.async.cg.shared.global [%0], [%1], 16;" :: "r"(dst), "l"(src) : "memory")
#define CP_COMMIT()    asm volatile("cp.async.commit_group;" ::: "memory")
#define CP_WAIT1()     asm volatile("cp.async.wait_group 1;" ::: "memory")
#define CP_WAIT0()     asm volatile("cp.async.wait_group 0;" ::: "memory")

__device__ __forceinline__ uint32_t smem_u32(const void* p) {
    uint32_t a;
    asm("{ .reg .u64 t; cvta.to.shared.u64 t, %1; cvt.u32.u64 %0, t; }" : "=r"(a) : "l"(p));
    return a;
}
__device__ __forceinline__ void mma4(float* c, float4 a, float b0, float b1) {
    asm volatile(
        "mma.sync.aligned.m16n8k8.row.col.f32.tf32.tf32.f32 "
        "{%0,%1,%2,%3}, {%4,%5,%6,%7}, {%8,%9}, {%0,%1,%2,%3};"
        : "+f"(c[0]), "+f"(c[1]), "+f"(c[2]), "+f"(c[3])
        : "r"(__float_as_uint(a.x)), "r"(__float_as_uint(a.y)),
          "r"(__float_as_uint(a.z)), "r"(__float_as_uint(a.w)),
          "r"(__float_as_uint(b0)), "r"(__float_as_uint(b1)));
}

// degree-3 basis, verbatim reference recursion
__device__ __forceinline__ void eval_basis(float xv, const float* __restrict__ k,
                                           const float* __restrict__ rd,
                                           float* __restrict__ bb)
{
    float t[11];
    #pragma unroll
    for (int j = 0; j < 11; j++)
        t[j] = (xv >= k[j] && xv < k[j + 1]) ? 1.0f : 0.0f;
    #pragma unroll
    for (int j = 0; j < 10; j++)
        t[j] = (xv - k[j]) * rd[j] * t[j] + (k[j + 2] - xv) * rd[j + 1] * t[j + 1];
    #pragma unroll
    for (int j = 0; j < 9; j++)
        t[j] = (xv - k[j]) * rd[j] * t[j] + (k[j + 3] - xv) * rd[j + 2] * t[j + 1];
    #pragma unroll
    for (int j = 0; j < 8; j++)
        bb[j] = f2tf32((xv - k[j]) * rd[j] * t[j] + (k[j + 4] - xv) * rd[j + 3] * t[j + 1]);
}

// ---------------- kernel 1: knot precompute ----------------
__global__ void grid_precompute_kernel(const float* __restrict__ steps_log,
                                       const float* __restrict__ grid_start)
{
    int i = blockIdx.x * blockDim.x + threadIdx.x;
    if (i >= IN_DIM) return;
    float kn[N_KNOTS];
    kn[0] = grid_start[i];
    float acc = kn[0];
    #pragma unroll
    for (int j = 0; j < N_KNOTS - 1; j++) {
        float v  = steps_log[i * (N_KNOTS - 1) + j];
        float sp = fmaxf(v, 0.0f) + log1pf(expf(-fabsf(v)));
        acc += sp;
        kn[j + 1] = acc;
    }
    #pragma unroll
    for (int j = 0; j < N_KNOTS; j++) g_knots[i * N_KNOTS + j] = kn[j];
    #pragma unroll
    for (int j = 0; j < N_KNOTS - 1; j++)
        g_rden[i * (N_KNOTS - 1) + j] = 1.0f / (kn[j + 1] - kn[j] + 1e-8f);
}

// ---------------- kernel 2: weights -> fragment-major 64-col slabs ----------------
// grid (72, 8): g<64 spline windows, g>=64 base windows; Tn = 64-col tile.
__global__ __launch_bounds__(256)
void convert_B_kernel(const float* __restrict__ coeffs,
                      const float* __restrict__ bw)
{
    const int t = threadIdx.x, g = blockIdx.x, Tn = blockIdx.y;
    const int dl = t >> 5, pr = t & 31;           // 8 windows x 32 col-pairs
    const int p16 = pr >> 3, p8 = pr & 7;
    const int o0 = Tn * 64 + p16 * 16 + p8, o1 = o0 + 8;
    float4 a0, a1, b0, b1;
    int window;
    if (g < 64) {
        const int d = g * 8 + dl;
        const float4* p0 = (const float4*)(coeffs + (size_t)o0 * 4096 + d * 8);
        const float4* p1 = (const float4*)(coeffs + (size_t)o1 * 4096 + d * 8);
        a0 = p0[0]; b0 = p0[1]; a1 = p1[0]; b1 = p1[1];
        window = d;
    } else {
        const int w = (g - 64) * 8 + dl;
        const float4* p0 = (const float4*)(bw + (size_t)o0 * 512 + w * 8);
        const float4* p1 = (const float4*)(bw + (size_t)o1 * 512 + w * 8);
        a0 = p0[0]; b0 = p0[1]; a1 = p1[0]; b1 = p1[1];
        window = 512 + w;
    }
    float4* dst = (float4*)(g_B + ((size_t)Tn * W_TOTAL + window) * 512
                            + p16 * 128 + p8 * 16);
    dst[0] = make_float4(f2tf32(a0.x), f2tf32(a1.x), f2tf32(b0.x), f2tf32(b1.x));
    dst[1] = make_float4(f2tf32(a0.y), f2tf32(a1.y), f2tf32(b0.y), f2tf32(b1.y));
    dst[2] = make_float4(f2tf32(a0.z), f2tf32(a1.z), f2tf32(b0.z), f2tf32(b1.z));
    dst[3] = make_float4(f2tf32(a0.w), f2tf32(a1.w), f2tf32(b0.w), f2tf32(b1.w));
}

// ---------------- kernel 3: A slabs (basis + silu), direct fragment writes ----------------
__global__ __launch_bounds__(256)
void gen_A_kernel(const float* __restrict__ x)
{
    __shared__ float sh[128 * 65];
    const int t = threadIdx.x, g = blockIdx.x, Tm = blockIdx.y;

    if (g < 64) {
        float* xs = sh;                         // [row][dl] stride 9
        float* kk = sh + 1152;
        float* rr = sh + 1152 + 96;
        #pragma unroll
        for (int it = 0; it < 4; it++) {
            const int idx = it * 256 + t;
            const int row = idx >> 3, dl = idx & 7;
            xs[row * 9 + dl] = __ldg(x + (size_t)(Tm * 128 + row) * IN_DIM + g * 8 + dl);
        }
        if (t < 96)               kk[t]      = g_knots[g * 8 * N_KNOTS + t];
        else if (t < 96 + 88)     rr[t - 96] = g_rden[g * 8 * (N_KNOTS - 1) + (t - 96)];
        __syncthreads();

        #pragma unroll
        for (int m = 0; m < 2; m++) {
            const int i  = m * 256 + t;
            const int dl = i >> 6, pr = i & 63;
            const int p16 = pr >> 3, p8 = pr & 7;
            const int row0 = p16 * 16 + p8;
            float bb0[8], bb1[8];
            eval_basis(xs[row0 * 9 + dl],       kk + dl * 12, rr + dl * 11, bb0);
            eval_basis(xs[(row0 + 8) * 9 + dl], kk + dl * 12, rr + dl * 11, bb1);
            float4* dst = (float4*)(g_A + ((size_t)Tm * W_TOTAL + g * 8 + dl) * 1024
                                    + p16 * 128 + p8 * 16);
            #pragma unroll
            for (int j = 0; j < 4; j++)
                dst[j] = make_float4(bb0[j], bb1[j], bb0[j + 4], bb1[j + 4]);
        }
    } else {
        const int d0 = (g - 64) * 64;
        #pragma unroll
        for (int it = 0; it < 32; it++) {
            const int idx = it * 256 + t;
            const int row = idx >> 6, dd = idx & 63;
            sh[row * 65 + dd] = __ldg(x + (size_t)(Tm * 128 + row) * IN_DIM + d0 + dd);
        }
        __syncthreads();

        #pragma unroll
        for (int m = 0; m < 2; m++) {
            const int i  = m * 256 + t;
            const int wl = i >> 6, pr = i & 63;
            const int p16 = pr >> 3, p8 = pr & 7;
            const int row0 = p16 * 16 + p8;
            float s0[8], s1[8];
            #pragma unroll
            for (int c = 0; c < 8; c++) {
                const float v0 = sh[row0 * 65 + wl * 8 + c];
                const float v1 = sh[(row0 + 8) * 65 + wl * 8 + c];
                s0[c] = f2tf32(v0 / (1.0f + expf(-v0)));
                s1[c] = f2tf32(v1 / (1.0f + expf(-v1)));
            }
            float4* dst = (float4*)(g_A + ((size_t)Tm * W_TOTAL + 512 + (g - 64) * 8 + wl) * 1024
                                    + p16 * 128 + p8 * 16);
            #pragma unroll
            for (int j = 0; j < 4; j++)
                dst[j] = make_float4(s0[j], s1[j], s0[j + 4], s1[j + 4]);
        }
    }
}

// ---------------- kernel 4: tf32 GEMM, CTA 128x64, warp 32x32, 3 CTAs/SM ----------------
__global__ __launch_bounds__(NTHREADS, 3)
void kan_gemm_kernel(const float* __restrict__ x,
                     const float* __restrict__ res_scale,
                     float* __restrict__ out)
{
    extern __shared__ float smem[];
    const int t = threadIdx.x, warp = t >> 5, lane = t & 31;
    const int q = lane >> 2, r = lane & 3;
    const int warpM = warp >> 1, warpN = warp & 1;        // 4 x 2 warps, 32x32 tiles
    const int Tn = blockIdx.x, Tm = blockIdx.y;           // Tn fastest -> A L2 reuse
    const int m_blk = Tm * 128, n_blk = Tn * 64;

    const float* Ab = g_A + (size_t)Tm * (W_TOTAL * 1024);
    const float* Bb = g_B + (size_t)Tn * (W_TOTAL * 512);
    const uint32_t sb = smem_u32(smem);

    auto loader = [&](int kt, int stage) {
        const float* as = Ab + (size_t)kt * 4096;
        const float* bs = Bb + (size_t)kt * 2048;
        const uint32_t sa = sb + stage * (STAGE_F * 4);
        #pragma unroll
        for (int i = 0; i < 4; i++) CP16(sa + (i * 256 + t) * 16, as + (i * 256 + t) * 4);
        #pragma unroll
        for (int i = 0; i < 2; i++) CP16(sa + 16384 + (i * 256 + t) * 16, bs + (i * 256 + t) * 4);
        CP_COMMIT();
    };

    float acc[2][4][4];
    #pragma unroll
    for (int i = 0; i < 2; i++)
        #pragma unroll
        for (int j = 0; j < 4; j++)
            #pragma unroll
            for (int v = 0; v < 4; v++) acc[i][j][v] = 0.0f;

    loader(0, 0);
    loader(1, 1);

    auto tile_step = [&](int kt, int stage, int load_stage) {
        if (kt < NTILES - 1) CP_WAIT1(); else CP_WAIT0();
        __syncthreads();
        if (kt + 2 < NTILES) loader(kt + 2, load_stage);

        const float* As = smem + stage * STAGE_F;
        const float* Bs = As + 4096;
        #pragma unroll
        for (int ws = 0; ws < 4; ws++) {
            const float4 a0 = *(const float4*)(As + ws * 1024 + (warpM * 2 + 0) * 128 + lane * 4);
            const float4 a1 = *(const float4*)(As + ws * 1024 + (warpM * 2 + 1) * 128 + lane * 4);
            const float4 b0 = *(const float4*)(Bs + ws * 512 + (warpN * 2 + 0) * 128 + lane * 4);
            const float4 b1 = *(const float4*)(Bs + ws * 512 + (warpN * 2 + 1) * 128 + lane * 4);
            mma4(acc[0][0], a0, b0.x, b0.z); mma4(acc[0][1], a0, b0.y, b0.w);
            mma4(acc[0][2], a0, b1.x, b1.z); mma4(acc[0][3], a0, b1.y, b1.w);
            mma4(acc[1][0], a1, b0.x, b0.z); mma4(acc[1][1], a1, b0.y, b0.w);
            mma4(acc[1][2], a1, b1.x, b1.z); mma4(acc[1][3], a1, b1.y, b1.w);
        }
    };

    #pragma unroll 1
    for (int kt = 0; kt < NTILES; kt += 3) {   // 144 % 3 == 0
        tile_step(kt,     0, 2);
        tile_step(kt + 1, 1, 0);
        tile_step(kt + 2, 2, 1);
    }

    // ---- epilogue: + rs*x, tanh ----
    const float rs = __ldg(res_scale);
    #pragma unroll
    for (int mf = 0; mf < 2; mf++) {
        #pragma unroll
        for (int rr2 = 0; rr2 < 2; rr2++) {
            const int rowg = m_blk + warpM * 32 + mf * 16 + rr2 * 8 + q;
            #pragma unroll
            for (int nf = 0; nf < 4; nf++) {
                const int col = n_blk + warpN * 32 + nf * 8 + r * 2;
                const size_t idx = (size_t)rowg * OUT_DIM + col;
                const float2 xv = __ldg((const float2*)(x + idx));
                float2 o;
                o.x = tanhf(acc[mf][nf][rr2 * 2 + 0] + rs * xv.x);
                o.y = tanhf(acc[mf][nf][rr2 * 2 + 1] + rs * xv.y);
                *(float2*)(out + idx) = o;
            }
        }
    }
}

// ---------------------------------------------------------------------------
extern "C" void kernel_launch(void* const* d_in, const int* in_sizes, int n_in,
                              void* d_out, int out_size)
{
    const float* x           = (const float*)d_in[0];
    const float* coeffs      = (const float*)d_in[1];
    const float* base_weight = (const float*)d_in[2];
    const float* steps_log   = (const float*)d_in[3];
    const float* grid_start  = (const float*)d_in[4];
    const float* res_scale   = (const float*)d_in[5];
    float* out = (float*)d_out;

    grid_precompute_kernel<<<2, 256>>>(steps_log, grid_start);
    convert_B_kernel<<<dim3(72, 8), 256>>>(coeffs, base_weight);
    gen_A_kernel<<<dim3(72, 128), 256>>>(x);

    cudaFuncSetAttribute(kan_gemm_kernel,
                         cudaFuncAttributeMaxDynamicSharedMemorySize, SMEM_BYTES);
    kan_gemm_kernel<<<dim3(8, 128), NTHREADS, SMEM_BYTES>>>(x, res_scale, out);
}